// round 12
// baseline (speedup 1.0000x reference)
#include <cuda_runtime.h>
#include <math.h>
#include <stdint.h>

#define EPSV 1e-5f
typedef unsigned long long ull;

// ---------------- helpers -----------------------------------------------------
static __device__ __forceinline__ ull pk2(float lo, float hi) {
    ull r; asm("mov.b64 %0,{%1,%2};" : "=l"(r) : "f"(lo), "f"(hi)); return r;
}
static __device__ __forceinline__ void upk2(ull v, float& lo, float& hi) {
    asm("mov.b64 {%0,%1},%2;" : "=f"(lo), "=f"(hi) : "l"(v));
}
static __device__ __forceinline__ ull f2fma(ull a, ull b, ull c) {
    ull r; asm("fma.rn.f32x2 %0,%1,%2,%3;" : "=l"(r) : "l"(a), "l"(b), "l"(c)); return r;
}
static __device__ __forceinline__ ull f2add(ull a, ull b) {
    ull r; asm("add.rn.f32x2 %0,%1,%2;" : "=l"(r) : "l"(a), "l"(b)); return r;
}
static __device__ __forceinline__ float tf32r(float v) {
    unsigned u; asm("cvt.rna.tf32.f32 %0, %1;" : "=r"(u) : "f"(v));
    return __uint_as_float(u);
}

// ---------------- scratch -----------------------------------------------------
__device__ float g_xt[1 * 16 * 16 * 1024];
__device__ float g_h1[16 * 14 * 14 * 1024];
__device__ float g_h2[32 * 12 * 12 * 1024];
__device__ float g_h3[64 * 10 * 10 * 1024];          // pre-BN (BN3 fused in FC)
__device__ float g_stats[224];
__device__ float g_part[25 * 10 * 1024];
__device__ ull   g_w1p[196 * 16 * 10];               // LC1 packed {w,w}
// tf32 fragment-ordered weights: idx = (((loc*NW+w)*NSTEP+ks)*32+lane)*4+j
__device__ float g_w2f[144 * 2 * 18 * 32 * 4];
__device__ float g_w3f[100 * 4 * 36 * 32 * 4];

// ---------------- fused prep: transpose + zero stats + weight pack ------------
__global__ void prep_kernel(const float* __restrict__ x,
                            const float* __restrict__ W1,
                            const float* __restrict__ W2,
                            const float* __restrict__ W3) {
    int bid = blockIdx.x;
    if (bid < 256) {
        __shared__ float tile[32][33];
        int bx = bid % 8, by = bid / 8;
        int tx = threadIdx.x % 32, ty = threadIdx.x / 32;
        for (int r = 0; r < 4; r++) {
            int p = bx * 32 + tx;
            int b = by * 32 + ty + r * 8;
            tile[ty + r * 8][tx] = x[b * 256 + p];
        }
        __syncthreads();
        for (int r = 0; r < 4; r++) {
            int p2 = bx * 32 + ty + r * 8;
            int b2 = by * 32 + tx;
            g_xt[p2 * 1024 + b2] = tile[tx][ty + r * 8];
        }
        return;
    }
    if (bid == 256) {
        if (threadIdx.x < 224) g_stats[threadIdx.x] = 0.f;
        return;
    }
    long idx = (long)(bid - 257) * 256 + threadIdx.x;
    if (idx < 28224) {
        int k = idx % 9, o = (idx / 9) % 16, loc = idx / 144;
        float w = W1[(((o * 1) * 14 + loc / 14) * 14 + loc % 14) * 9 + k];
        g_w1p[(loc * 16 + o) * 10 + k] = pk2(w, w);
        return;
    }
    idx -= 28224;
    if (idx < 663552) {       // LC2 fragments: NW=2, NSTEP=18
        int j = idx & 3, lane = (idx >> 2) & 31;
        int ks = (int)((idx >> 7) % 18);
        int ot = (int)((idx / (128 * 18)) & 1);
        int loc = (int)(idx / (128 * 18 * 2));
        int g = lane >> 2, tig = lane & 3;
        int o = ot * 16 + (j & 1) * 8 + g;
        int k = ks * 8 + tig + (j >> 1) * 4;
        int c = k / 9, ij = k % 9;
        float w = W2[((((o * 16 + c) * 12 + loc / 12) * 12 + loc % 12)) * 9 + ij];
        g_w2f[idx] = tf32r(w);
        return;
    }
    idx -= 663552;
    if (idx < 1843200) {      // LC3 fragments: NW=4, NSTEP=36
        int j = idx & 3, lane = (idx >> 2) & 31;
        int ks = (int)((idx >> 7) % 36);
        int ot = (int)((idx / (128 * 36)) & 3);
        int loc = (int)(idx / 18432);
        int g = lane >> 2, tig = lane & 3;
        int o = ot * 16 + (j & 1) * 8 + g;
        int k = ks * 8 + tig + (j >> 1) * 4;
        int c = k / 9, ij = k % 9;
        float w = W3[((((o * 32 + c) * 10 + loc / 10) * 10 + loc % 10)) * 9 + ij];
        g_w3f[idx] = tf32r(w);
    }
}

// ---------------- LC1 (C=1): scalar f32x2 --------------------------------------
__global__ void __launch_bounds__(64, 8)
lc1_kernel(const float* __restrict__ in, const ull* __restrict__ WP,
           const float* __restrict__ bias, float* __restrict__ out,
           float* __restrict__ stats_out) {
    const int OH = 14, HIN = 16;
    const int loc  = blockIdx.x;
    const int lane = threadIdx.x;
    const int b0   = blockIdx.y * 256 + lane * 2;
    const int tid  = threadIdx.y * 32 + lane;
    const int ogrp = threadIdx.y;

    __shared__ ull Ws2[16 * 10];
    const ull* wsrc = WP + (size_t)loc * 160;
    for (int lin = tid; lin < 160; lin += 64) Ws2[lin] = wsrc[lin];
    __syncthreads();

    ull acc[8][4];
#pragma unroll
    for (int o = 0; o < 8; o++)
#pragma unroll
        for (int m = 0; m < 4; m++) acc[o][m] = 0ull;

    const ull* wp = Ws2 + ogrp * 8 * 10;
    const float* cp = in + ((size_t)(loc / OH) * HIN + (loc % OH)) * 1024 + b0;

#pragma unroll
    for (int p = 0; p < 4; p++) {
        const int ij0 = 2 * p, ij1 = 2 * p + 1;
        const int off0 = ((ij0 / 3) * HIN + (ij0 % 3)) * 1024;
        const int off1 = ((ij1 / 3) * HIN + (ij1 % 3)) * 1024;
        ull v0[4], v1[4];
#pragma unroll
        for (int m = 0; m < 4; m++) v0[m] = *(const ull*)(cp + off0 + 64 * m);
#pragma unroll
        for (int m = 0; m < 4; m++) v1[m] = *(const ull*)(cp + off1 + 64 * m);
#pragma unroll
        for (int o = 0; o < 8; o++) {
            ulonglong2 w = *(const ulonglong2*)&wp[o * 10 + 2 * p];
#pragma unroll
            for (int m = 0; m < 4; m++) acc[o][m] = f2fma(v0[m], w.x, acc[o][m]);
#pragma unroll
            for (int m = 0; m < 4; m++) acc[o][m] = f2fma(v1[m], w.y, acc[o][m]);
        }
    }
    {
        const int off = (2 * HIN + 2) * 1024;
        ull v[4];
#pragma unroll
        for (int m = 0; m < 4; m++) v[m] = *(const ull*)(cp + off + 64 * m);
#pragma unroll
        for (int o = 0; o < 8; o++) {
            ull w2 = wp[o * 10 + 8];
#pragma unroll
            for (int m = 0; m < 4; m++) acc[o][m] = f2fma(v[m], w2, acc[o][m]);
        }
    }

#pragma unroll
    for (int o = 0; o < 8; o++) {
        int og = ogrp * 8 + o;
        float bb = __ldg(&bias[og * 196 + loc]);
        ull b2 = pk2(bb, bb);
        float* op = out + ((size_t)og * 196 + loc) * 1024 + b0;
        ull s2 = 0ull, q2 = 0ull;
#pragma unroll
        for (int m = 0; m < 4; m++) {
            ull r = f2add(acc[o][m], b2);
            *(ull*)(op + 64 * m) = r;
            s2 = f2add(s2, r);
            q2 = f2fma(r, r, q2);
        }
        float sl, sh, ql, qh;
        upk2(s2, sl, sh); upk2(q2, ql, qh);
        float s = sl + sh, q = ql + qh;
#pragma unroll
        for (int off = 16; off > 0; off >>= 1) {
            s += __shfl_down_sync(0xffffffffu, s, off);
            q += __shfl_down_sync(0xffffffffu, q, off);
        }
        if (lane == 0) {
            atomicAdd(&stats_out[og * 2 + 0], s);
            atomicAdd(&stats_out[og * 2 + 1], q);
        }
    }
}

// ---------------- tensor-core LC (tf32 mma.sync), NB n-tiles per warp ----------
// grid (OH*OH, 1024/(NB*8))
template <int C, int HIN, int OH, int O_TOT, int NB, int MINB>
__global__ void __launch_bounds__((O_TOT / 16) * 32, MINB)
lc_tc_kernel(const float* __restrict__ in, const float* __restrict__ WF,
             const float* __restrict__ bias, float* __restrict__ out,
             float* __restrict__ stats_out) {
    constexpr int NW    = O_TOT / 16;
    constexpr int NTH   = NW * 32;
    constexpr int KK    = C * 9;
    constexpr int NSTEP = KK / 8;
    constexpr int NSTG  = C / 8;
    constexpr int RPS   = 72;            // k-rows per stage (8 channels)
    constexpr int BATCH = NB * 8;        // batch per warp/block
    constexpr int BP    = BATCH + 8;     // pitch: BP % 32 == 8 -> conflict-free
    constexpr int F4R   = BATCH / 4;     // float4 per row

    extern __shared__ __align__(16) unsigned char smraw[];
    float* buf  = (float*)smraw;                      // [2][RPS*BP]
    int* kbase  = (int*)(buf + 2 * RPS * BP);         // [KK]

    const int loc   = blockIdx.x, y = loc / OH, x = loc % OH;
    const int b_blk = blockIdx.y * BATCH;
    const int lane  = threadIdx.x, w = threadIdx.y;
    const int tid   = w * 32 + lane;
    const int g     = lane >> 2, tig = lane & 3;

    for (int k = tid; k < KK; k += NTH) {
        int c = k / 9, ij = k % 9;
        kbase[k] = ((c * HIN + y + ij / 3) * HIN + (x + ij % 3)) * 1024 + b_blk;
    }
    __syncthreads();

#define STAGE(ST) do { \
    const int _r0 = (ST) * RPS; \
    float* _db = buf + ((ST) & 1) * RPS * BP; \
    _Pragma("unroll") \
    for (int _it = 0; _it < RPS * F4R / NTH; _it++) { \
        int _t = tid + _it * NTH; \
        int _r = _t / F4R, _c = _t % F4R; \
        const float* _src = in + kbase[_r0 + _r] + _c * 4; \
        unsigned _d = (unsigned)__cvta_generic_to_shared(_db + _r * BP + _c * 4); \
        asm volatile("cp.async.cg.shared.global [%0], [%1], 16;" :: "r"(_d), "l"(_src)); \
    } \
    asm volatile("cp.async.commit_group;"); } while (0)

    STAGE(0);

    float acc[NB][4];
#pragma unroll
    for (int nt = 0; nt < NB; nt++)
#pragma unroll
        for (int j = 0; j < 4; j++) acc[nt][j] = 0.f;

    const float* wf = WF + ((size_t)(loc * NW + w) * NSTEP * 32 + lane) * 4;

#pragma unroll 1
    for (int st = 0; st < NSTG; st++) {
        asm volatile("cp.async.wait_group 0;");
        __syncthreads();
        if (st + 1 < NSTG) STAGE(st + 1);
        const float* bb = buf + (st & 1) * RPS * BP;
#pragma unroll
        for (int kl = 0; kl < 9; kl++) {
            const int ks = st * 9 + kl;
            float4 afv = *(const float4*)(wf + (size_t)ks * 128);
            unsigned a0 = __float_as_uint(afv.x), a1 = __float_as_uint(afv.y);
            unsigned a2 = __float_as_uint(afv.z), a3 = __float_as_uint(afv.w);
            const float* br0 = bb + (kl * 8 + tig) * BP + g;
            const float* br1 = br0 + 4 * BP;
#pragma unroll
            for (int nt = 0; nt < NB; nt++) {
                unsigned b0 = __float_as_uint(br0[nt * 8]);
                unsigned b1 = __float_as_uint(br1[nt * 8]);
                asm volatile(
                    "mma.sync.aligned.m16n8k8.row.col.f32.tf32.tf32.f32 "
                    "{%0,%1,%2,%3}, {%4,%5,%6,%7}, {%8,%9}, {%0,%1,%2,%3};"
                    : "+f"(acc[nt][0]), "+f"(acc[nt][1]),
                      "+f"(acc[nt][2]), "+f"(acc[nt][3])
                    : "r"(a0), "r"(a1), "r"(a2), "r"(a3), "r"(b0), "r"(b1));
            }
        }
    }
#undef STAGE

    // epilogue: bias + store pre-BN + BN stats
    const int olo = w * 16 + g, ohi = olo + 8;
    float blo = __ldg(&bias[olo * OH * OH + loc]);
    float bhi = __ldg(&bias[ohi * OH * OH + loc]);
    float* plo = out + ((size_t)olo * OH * OH + loc) * 1024 + b_blk + 2 * tig;
    float* phi = out + ((size_t)ohi * OH * OH + loc) * 1024 + b_blk + 2 * tig;
    float slo = 0.f, qlo = 0.f, shi = 0.f, qhi = 0.f;
#pragma unroll
    for (int nt = 0; nt < NB; nt++) {
        float d0 = acc[nt][0] + blo, d1 = acc[nt][1] + blo;
        float d2 = acc[nt][2] + bhi, d3 = acc[nt][3] + bhi;
        *(float2*)(plo + nt * 8) = make_float2(d0, d1);
        *(float2*)(phi + nt * 8) = make_float2(d2, d3);
        slo += d0 + d1; qlo += d0 * d0 + d1 * d1;
        shi += d2 + d3; qhi += d2 * d2 + d3 * d3;
    }
#pragma unroll
    for (int m = 1; m < 4; m <<= 1) {
        slo += __shfl_xor_sync(0xffffffffu, slo, m);
        qlo += __shfl_xor_sync(0xffffffffu, qlo, m);
        shi += __shfl_xor_sync(0xffffffffu, shi, m);
        qhi += __shfl_xor_sync(0xffffffffu, qhi, m);
    }
    if (tig == 0) {
        atomicAdd(&stats_out[olo * 2 + 0], slo);
        atomicAdd(&stats_out[olo * 2 + 1], qlo);
        atomicAdd(&stats_out[ohi * 2 + 0], shi);
        atomicAdd(&stats_out[ohi * 2 + 1], qhi);
    }
}

// ---------------- BN apply + ReLU (+tf32 round), in place ----------------------
template <int TF32R>
__global__ void bn_relu_kernel(const float* __restrict__ stats, const float* __restrict__ g,
                               const float* __restrict__ be, float* __restrict__ data,
                               int per_chan, float inv_n) {
    int ch = blockIdx.y;
    float m  = stats[ch * 2 + 0] * inv_n;
    float v  = stats[ch * 2 + 1] * inv_n - m * m;
    float sc = g[ch] * rsqrtf(v + EPSV);
    float sh = be[ch] - sc * m;
    float4* p = (float4*)(data + (size_t)ch * per_chan);
    int i = blockIdx.x * blockDim.x + threadIdx.x;
    float4 t = p[i];
    t.x = fmaxf(fmaf(t.x, sc, sh), 0.f);
    t.y = fmaxf(fmaf(t.y, sc, sh), 0.f);
    t.z = fmaxf(fmaf(t.z, sc, sh), 0.f);
    t.w = fmaxf(fmaf(t.w, sc, sh), 0.f);
    if (TF32R) { t.x = tf32r(t.x); t.y = tf32r(t.y); t.z = tf32r(t.z); t.w = tf32r(t.w); }
    p[i] = t;
}

// ---------------- FC with fused BN3 + tanh -------------------------------------
__global__ void fc_partial_kernel(const float* __restrict__ h, const float* __restrict__ Wfc,
                                  const float* __restrict__ stats, const float* __restrict__ g,
                                  const float* __restrict__ be, float inv_n) {
    const int FCH = 256;
    int b  = blockIdx.x * 128 + threadIdx.x;
    int f0 = blockIdx.y * FCH;
    __shared__ float Wsm[10 * FCH];
    __shared__ float fsc[FCH], fsh[FCH];
    for (int i = threadIdx.x; i < 10 * FCH; i += 128) {
        int t = i / FCH, f = i % FCH;
        Wsm[i] = Wfc[t * 6400 + f0 + f];
    }
    for (int f = threadIdx.x; f < FCH; f += 128) {
        int ch = (f0 + f) / 100;
        float m  = stats[ch * 2 + 0] * inv_n;
        float v  = stats[ch * 2 + 1] * inv_n - m * m;
        float sc = g[ch] * rsqrtf(v + EPSV);
        fsc[f] = sc;
        fsh[f] = be[ch] - sc * m;
    }
    __syncthreads();
    float acc[10];
#pragma unroll
    for (int t = 0; t < 10; t++) acc[t] = 0.f;
    for (int f = 0; f < FCH; f++) {
        float v = h[(size_t)(f0 + f) * 1024 + b];
        v = tanhf(fmaf(v, fsc[f], fsh[f]));
#pragma unroll
        for (int t = 0; t < 10; t++) acc[t] = fmaf(v, Wsm[t * FCH + f], acc[t]);
    }
#pragma unroll
    for (int t = 0; t < 10; t++)
        g_part[((size_t)blockIdx.y * 10 + t) * 1024 + b] = acc[t];
}

__global__ void fc_reduce_kernel(const float* __restrict__ fcb, float* __restrict__ out) {
    int idx = blockIdx.x * blockDim.x + threadIdx.x;
    if (idx >= 10240) return;
    int b = idx / 10, t = idx % 10;
    float s = fcb[t];
#pragma unroll
    for (int c = 0; c < 25; c++) s += g_part[((size_t)c * 10 + t) * 1024 + b];
    out[b * 10 + t] = s;
}

// ---------------- launch ---------------------------------------------------------
extern "C" void kernel_launch(void* const* d_in, const int* in_sizes, int n_in,
                              void* d_out, int out_size) {
    const float* x   = (const float*)d_in[0];
    const float* W1  = (const float*)d_in[1];
    const float* b1  = (const float*)d_in[2];
    const float* g1  = (const float*)d_in[3];
    const float* be1 = (const float*)d_in[4];
    const float* W2  = (const float*)d_in[5];
    const float* b2  = (const float*)d_in[6];
    const float* g2  = (const float*)d_in[7];
    const float* be2 = (const float*)d_in[8];
    const float* W3  = (const float*)d_in[9];
    const float* b3  = (const float*)d_in[10];
    const float* g3  = (const float*)d_in[11];
    const float* be3 = (const float*)d_in[12];
    const float* fcW = (const float*)d_in[13];
    const float* fcb = (const float*)d_in[14];
    float* out = (float*)d_out;

    float *p_xt, *p_h1, *p_h2, *p_h3, *p_stats, *p_w2f, *p_w3f;
    ull* p_w1p;
    cudaGetSymbolAddress((void**)&p_xt, g_xt);
    cudaGetSymbolAddress((void**)&p_h1, g_h1);
    cudaGetSymbolAddress((void**)&p_h2, g_h2);
    cudaGetSymbolAddress((void**)&p_h3, g_h3);
    cudaGetSymbolAddress((void**)&p_stats, g_stats);
    cudaGetSymbolAddress((void**)&p_w1p, g_w1p);
    cudaGetSymbolAddress((void**)&p_w2f, g_w2f);
    cudaGetSymbolAddress((void**)&p_w3f, g_w3f);

    // dynamic smem: double input buffer + kbase table
    const int smt2 = 2 * 72 * 72 * 4 + 144 * 4;     // LC2 (NB=8):  ~41.6 KB
    const int smt3 = 2 * 72 * 136 * 4 + 288 * 4;    // LC3 (NB=16): ~77.7 KB
    cudaFuncSetAttribute((const void*)lc_tc_kernel<16, 14, 12, 32, 8, 5>,
                         cudaFuncAttributeMaxDynamicSharedMemorySize, smt2);
    cudaFuncSetAttribute((const void*)lc_tc_kernel<32, 12, 10, 64, 16, 2>,
                         cudaFuncAttributeMaxDynamicSharedMemorySize, smt3);

    int wblocks = 257 + (28224 + 663552 + 1843200 + 255) / 256;
    prep_kernel<<<wblocks, 256>>>(x, W1, W2, W3);

    // #1 LC1, #2 bn1(tf32 round), #3 LC2-tensor (profiled control, expect ~25us)
    lc1_kernel<<<dim3(196, 4), dim3(32, 2)>>>(p_xt, p_w1p, b1, p_h1, p_stats + 0);
    bn_relu_kernel<1><<<dim3(196, 16), 256>>>(p_stats + 0, g1, be1, p_h1,
                                              14 * 14 * 1024, 1.f / (14.f * 14.f * 1024.f));
    lc_tc_kernel<16, 14, 12, 32, 8, 5><<<dim3(144, 16), dim3(32, 2), smt2>>>(
        p_h1, p_w2f, b2, p_h2, p_stats + 32);
    bn_relu_kernel<1><<<dim3(144, 32), 256>>>(p_stats + 32, g2, be2, p_h2,
                                              12 * 12 * 1024, 1.f / (12.f * 12.f * 1024.f));
    // LC3: NB=16 (128 batch/warp), grid.y 8
    lc_tc_kernel<32, 12, 10, 64, 16, 2><<<dim3(100, 8), dim3(32, 4), smt3>>>(
        p_h2, p_w3f, b3, p_h3, p_stats + 96);

    fc_partial_kernel<<<dim3(8, 25), 128>>>(p_h3, fcW, p_stats + 96, g3, be3,
                                            1.f / (10.f * 10.f * 1024.f));
    fc_reduce_kernel<<<40, 256>>>(fcb, out);
}